// round 1
// baseline (speedup 1.0000x reference)
#include <cuda_runtime.h>
#include <cstdint>

#define SEQ   21
#define BDIM  8192
#define HDIM  1024
#define MTOT  (SEQ * BDIM)   // 172032

// Scratch (device globals: allocation-free rule)
__device__ float g_wc[(size_t)BDIM * HDIM];   // 32 MB: wc = c @ W
__device__ float g_scores[MTOT];              // per-(s,b) raw scores

__device__ __forceinline__ float to_tf32(float x) {
    uint32_t u;
    asm("cvt.rna.tf32.f32 %0, %1;" : "=r"(u) : "f"(x));
    return __uint_as_float(u);
}

__device__ __forceinline__ float fast_tanh(float x) {
    float r;
    asm("tanh.approx.f32 %0, %1;" : "=f"(r) : "f"(x));
    return r;
}

__device__ __forceinline__ void mma_tf32(
    float& d0, float& d1, float& d2, float& d3,
    uint32_t a0, uint32_t a1, uint32_t a2, uint32_t a3,
    uint32_t b0, uint32_t b1)
{
    asm volatile(
        "mma.sync.aligned.m16n8k8.row.col.f32.tf32.tf32.f32 "
        "{%0,%1,%2,%3}, {%4,%5,%6,%7}, {%8,%9}, {%0,%1,%2,%3};\n"
        : "+f"(d0), "+f"(d1), "+f"(d2), "+f"(d3)
        : "r"(a0), "r"(a1), "r"(a2), "r"(a3), "r"(b0), "r"(b1));
}

__global__ void zero_scores_kernel() {
    int i = blockIdx.x * blockDim.x + threadIdx.x;
    if (i < MTOT) g_scores[i] = 0.0f;
}

// ---------------------------------------------------------------------------
// TF32 GEMM, 128x128 CTA tile, BK=32, 8 warps (2 M x 4 N), warp tile 64x32.
// MODE 0: C = A @ Bm, store into g_wc                (A = c [BDIM,H])
// MODE 1: fused score epilogue:                      (A = allh [MTOT,H])
//         e = tanh(acc + wc[b,n] + bias[s,n]); score[r] += sum_n e * Wt[n]
// All dims divide the tile sizes exactly, so no bounds checks.
// ---------------------------------------------------------------------------
template <int MODE>
__global__ __launch_bounds__(256, 2)
void gemm_tf32_kernel(const float* __restrict__ A,
                      const float* __restrict__ Bm,
                      const float* __restrict__ bias,
                      const float* __restrict__ Wt)
{
    // Pitches chosen for conflict-free mma fragment loads:
    // As[m][k]: pitch 36 -> addr%32 = 4*grp + qid (distinct)
    // Bs[k][n]: pitch 136 -> addr%32 = 8*qid + 8*nt + grp (distinct per nt)
    __shared__ float As[128 * 36];
    __shared__ float Bs[32 * 136];

    const int tid   = threadIdx.x;
    const int lane  = tid & 31;
    const int wid   = tid >> 5;
    const int warpM = wid & 1;   // 0..1
    const int warpN = wid >> 1;  // 0..3
    const int grp   = lane >> 2; // 0..7
    const int qid   = lane & 3;  // 0..3

    const int rowBase = blockIdx.y * 128;
    const int colBase = blockIdx.x * 128;

    float acc[4][4][4];
#pragma unroll
    for (int i = 0; i < 4; i++)
#pragma unroll
        for (int j = 0; j < 4; j++)
#pragma unroll
            for (int k = 0; k < 4; k++) acc[i][j][k] = 0.0f;

    const float* Aptr = A + (size_t)rowBase * HDIM;
    const float* Bptr = Bm + colBase;

    for (int kb = 0; kb < HDIM; kb += 32) {
        // Stage A tile: 128 rows x 32 cols (1024 float4, 4 per thread)
#pragma unroll
        for (int j = 0; j < 4; j++) {
            int i  = tid + 256 * j;
            int r  = i >> 3;
            int c4 = (i & 7) << 2;
            float4 v = *(const float4*)(Aptr + (size_t)r * HDIM + kb + c4);
            v.x = to_tf32(v.x); v.y = to_tf32(v.y);
            v.z = to_tf32(v.z); v.w = to_tf32(v.w);
            *(float4*)(As + r * 36 + c4) = v;
        }
        // Stage B tile: 32 k-rows x 128 cols
#pragma unroll
        for (int j = 0; j < 4; j++) {
            int i  = tid + 256 * j;
            int kr = i >> 5;
            int c4 = (i & 31) << 2;
            float4 v = *(const float4*)(Bptr + (size_t)(kb + kr) * HDIM + c4);
            v.x = to_tf32(v.x); v.y = to_tf32(v.y);
            v.z = to_tf32(v.z); v.w = to_tf32(v.w);
            *(float4*)(Bs + kr * 136 + c4) = v;
        }
        __syncthreads();

#pragma unroll
        for (int kk = 0; kk < 4; kk++) {
            uint32_t af[4][4], bf[4][2];
#pragma unroll
            for (int mt = 0; mt < 4; mt++) {
                int rm = warpM * 64 + mt * 16;
                const float* p = As + (rm + grp) * 36 + kk * 8 + qid;
                af[mt][0] = __float_as_uint(p[0]);
                af[mt][1] = __float_as_uint(p[8 * 36]);
                af[mt][2] = __float_as_uint(p[4]);
                af[mt][3] = __float_as_uint(p[8 * 36 + 4]);
            }
#pragma unroll
            for (int nt = 0; nt < 4; nt++) {
                int cn = warpN * 32 + nt * 8 + grp;
                const float* p = Bs + (kk * 8 + qid) * 136 + cn;
                bf[nt][0] = __float_as_uint(p[0]);
                bf[nt][1] = __float_as_uint(p[4 * 136]);
            }
#pragma unroll
            for (int mt = 0; mt < 4; mt++)
#pragma unroll
                for (int nt = 0; nt < 4; nt++)
                    mma_tf32(acc[mt][nt][0], acc[mt][nt][1],
                             acc[mt][nt][2], acc[mt][nt][3],
                             af[mt][0], af[mt][1], af[mt][2], af[mt][3],
                             bf[nt][0], bf[nt][1]);
        }
        __syncthreads();
    }

    if (MODE == 0) {
        // store C tile to g_wc
#pragma unroll
        for (int mt = 0; mt < 4; mt++) {
            int r0 = rowBase + warpM * 64 + mt * 16 + grp;
#pragma unroll
            for (int nt = 0; nt < 4; nt++) {
                int c0 = colBase + warpN * 32 + nt * 8 + qid * 2;
                g_wc[(size_t)r0 * HDIM + c0]       = acc[mt][nt][0];
                g_wc[(size_t)r0 * HDIM + c0 + 1]   = acc[mt][nt][1];
                g_wc[(size_t)(r0 + 8) * HDIM + c0]     = acc[mt][nt][2];
                g_wc[(size_t)(r0 + 8) * HDIM + c0 + 1] = acc[mt][nt][3];
            }
        }
    } else {
        // fused score epilogue: scores[r] += sum_n tanh(acc + wc + bias) * Wt[n]
        float part[8];
#pragma unroll
        for (int i = 0; i < 8; i++) part[i] = 0.0f;

#pragma unroll
        for (int mt = 0; mt < 4; mt++) {
            int r0 = rowBase + warpM * 64 + mt * 16 + grp;
            int r1 = r0 + 8;
            int b0 = r0 & (BDIM - 1), s0 = r0 >> 13;
            int b1 = r1 & (BDIM - 1), s1 = r1 >> 13;
#pragma unroll
            for (int nt = 0; nt < 4; nt++) {
                int c0 = colBase + warpN * 32 + nt * 8 + qid * 2;
                float wt0 = Wt[c0], wt1 = Wt[c0 + 1];
                float e;
                e = fast_tanh(acc[mt][nt][0] + g_wc[(size_t)b0 * HDIM + c0]
                              + bias[s0 * HDIM + c0]);
                part[mt * 2] += e * wt0;
                e = fast_tanh(acc[mt][nt][1] + g_wc[(size_t)b0 * HDIM + c0 + 1]
                              + bias[s0 * HDIM + c0 + 1]);
                part[mt * 2] += e * wt1;
                e = fast_tanh(acc[mt][nt][2] + g_wc[(size_t)b1 * HDIM + c0]
                              + bias[s1 * HDIM + c0]);
                part[mt * 2 + 1] += e * wt0;
                e = fast_tanh(acc[mt][nt][3] + g_wc[(size_t)b1 * HDIM + c0 + 1]
                              + bias[s1 * HDIM + c0 + 1]);
                part[mt * 2 + 1] += e * wt1;
            }
        }
        // reduce across the 4 lanes (qid) sharing each row
#pragma unroll
        for (int i = 0; i < 8; i++) {
            part[i] += __shfl_xor_sync(0xffffffffu, part[i], 1);
            part[i] += __shfl_xor_sync(0xffffffffu, part[i], 2);
        }
        if (qid == 0) {
#pragma unroll
            for (int mt = 0; mt < 4; mt++) {
                int r0 = rowBase + warpM * 64 + mt * 16 + grp;
                atomicAdd(&g_scores[r0],     part[mt * 2]);
                atomicAdd(&g_scores[r0 + 8], part[mt * 2 + 1]);
            }
        }
    }
}

// ---------------------------------------------------------------------------
// Per-b softmax over SEQ scores + weighted sum of allh rows -> out[b, :]
// ---------------------------------------------------------------------------
__global__ __launch_bounds__(256)
void softmax_combine_kernel(const float* __restrict__ allh,
                            float* __restrict__ out)
{
    int b = blockIdx.x;
    __shared__ float s_alpha[32];

    if (threadIdx.x < 32) {
        int lane = threadIdx.x;
        float v = (lane < SEQ) ? g_scores[lane * BDIM + b] : -1e30f;
        float m = v;
#pragma unroll
        for (int o = 16; o > 0; o >>= 1)
            m = fmaxf(m, __shfl_xor_sync(0xffffffffu, m, o));
        float e = (lane < SEQ) ? __expf(v - m) : 0.0f;
        float sum = e;
#pragma unroll
        for (int o = 16; o > 0; o >>= 1)
            sum += __shfl_xor_sync(0xffffffffu, sum, o);
        s_alpha[lane] = e / sum;
    }
    __syncthreads();

    const float* hb = allh + (size_t)b * HDIM;
#pragma unroll
    for (int h0 = 0; h0 < HDIM; h0 += 256) {
        int h = h0 + threadIdx.x;
        float accv = 0.0f;
#pragma unroll
        for (int s = 0; s < SEQ; s++)
            accv += s_alpha[s] * hb[(size_t)s * BDIM * HDIM + h];
        out[(size_t)b * HDIM + h] = accv;
    }
}

extern "C" void kernel_launch(void* const* d_in, const int* in_sizes, int n_in,
                              void* d_out, int out_size)
{
    const float* c    = (const float*)d_in[0];  // [1, B, H]
    const float* allh = (const float*)d_in[1];  // [S, B, H]
    const float* W    = (const float*)d_in[2];  // [H, H]
    const float* V    = (const float*)d_in[3];  // [H, H]
    const float* bias = (const float*)d_in[4];  // [S, H]
    const float* Wt   = (const float*)d_in[5];  // [H, 1]
    float* out = (float*)d_out;                 // [1, B, H]

    (void)in_sizes; (void)n_in; (void)out_size;

    // 1) zero the score accumulator
    zero_scores_kernel<<<MTOT / 256, 256>>>();

    // 2) wc = c @ W   (grid: N tiles x M tiles = 8 x 64)
    gemm_tf32_kernel<0><<<dim3(HDIM / 128, BDIM / 128), 256>>>(c, W, nullptr, nullptr);

    // 3) fused vh GEMM + tanh + score reduction (grid: 8 x 1344)
    gemm_tf32_kernel<1><<<dim3(HDIM / 128, MTOT / 128), 256>>>(allh, V, bias, Wt);

    // 4) softmax over S and weighted combine
    softmax_combine_kernel<<<BDIM, 256>>>(allh, out);
}

// round 3
// speedup vs baseline: 1.3144x; 1.3144x over previous
#include <cuda_runtime.h>
#include <cuda_fp16.h>
#include <cstdint>

#define SEQ   21
#define BDIM  8192
#define HDIM  1024
#define MTOT  (SEQ * BDIM)   // 172032

#define BK    32
#define NKT   (HDIM / BK)    // 32
#define PITCH 36             // halves per smem row (72B) -> conflict-free frags

// ---- device scratch (allocation-free rule) ----
__device__ float g_wc[(size_t)BDIM * HDIM];   // 32 MB: wc = c @ W
__device__ float g_scores[MTOT];
__device__ float g_wt[(size_t)HDIM * HDIM];   // W^T  [n][k]
__device__ float g_vt[(size_t)HDIM * HDIM];   // V^T  [n][k]

__device__ __forceinline__ float fast_tanh(float x) {
    float r; asm("tanh.approx.f32 %0, %1;" : "=f"(r) : "f"(x)); return r;
}
__device__ __forceinline__ uint32_t pack_half2(float lo, float hi) {
    uint32_t r;
    asm("cvt.rn.f16x2.f32 %0, %1, %2;" : "=r"(r) : "f"(hi), "f"(lo));
    return r;
}
__device__ __forceinline__ void mma_f16(
    float& d0, float& d1, float& d2, float& d3,
    uint32_t a0, uint32_t a1, uint32_t a2, uint32_t a3,
    uint32_t b0, uint32_t b1)
{
    asm volatile(
        "mma.sync.aligned.m16n8k16.row.col.f32.f16.f16.f32 "
        "{%0,%1,%2,%3}, {%4,%5,%6,%7}, {%8,%9}, {%0,%1,%2,%3};\n"
        : "+f"(d0), "+f"(d1), "+f"(d2), "+f"(d3)
        : "r"(a0), "r"(a1), "r"(a2), "r"(a3), "r"(b0), "r"(b1));
}

__global__ void zero_scores_kernel() {
    int i = blockIdx.x * blockDim.x + threadIdx.x;
    if (i < MTOT) g_scores[i] = 0.0f;
}

__global__ void transpose_kernel(const float* __restrict__ in, float* __restrict__ out) {
    __shared__ float t[32][33];
    int x = blockIdx.x * 32 + threadIdx.x;
#pragma unroll
    for (int i = 0; i < 32; i += 8) {
        int y = blockIdx.y * 32 + threadIdx.y + i;
        t[threadIdx.y + i][threadIdx.x] = in[(size_t)y * HDIM + x];
    }
    __syncthreads();
    int x2 = blockIdx.y * 32 + threadIdx.x;
#pragma unroll
    for (int i = 0; i < 32; i += 8) {
        int y2 = blockIdx.x * 32 + threadIdx.y + i;
        out[(size_t)y2 * HDIM + x2] = t[threadIdx.x][threadIdx.y + i];
    }
}

// ---------------------------------------------------------------------------
// FP16 GEMM (fp32 accum), 128x128 CTA tile, BK=32, 8 warps (2M x 4N),
// warp tile 64x32, mma m16n8k16. Double-buffered smem + register prefetch.
//   A: [M][K] f32 row-major.  Bt: [N][K] f32 (transposed weight).
// MODE 0: C -> g_wc.
// MODE 1: e = tanh(C + wc[b,:] + bias[s,:]); scores[row] += e . Wt
// ---------------------------------------------------------------------------
template <int MODE>
__global__ __launch_bounds__(256, 2)
void gemm_f16_kernel(const float* __restrict__ A,
                     const float* __restrict__ Bt,
                     const float* __restrict__ bias,
                     const float* __restrict__ Wt)
{
    __shared__ __half As[2][128 * PITCH];
    __shared__ __half Bs[2][128 * PITCH];

    const int tid   = threadIdx.x;
    const int lane  = tid & 31;
    const int wid   = tid >> 5;
    const int warpM = wid & 1;   // 0..1
    const int warpN = wid >> 1;  // 0..3
    const int grp   = lane >> 2; // 0..7
    const int qid   = lane & 3;  // 0..3

    const int rowBase = blockIdx.y * 128;
    const int colBase = blockIdx.x * 128;

    // staging geometry: 1024 float4-chunks per 128x32 tile, 4 per thread
    const int srow = tid >> 3;          // base row (stride 32 over j)
    const int sc4  = (tid & 7) << 2;    // k offset (floats)

    const float* Aptr = A  + (size_t)rowBase * HDIM;
    const float* Bptr = Bt + (size_t)colBase * HDIM;

    float acc[4][4][4];
#pragma unroll
    for (int i = 0; i < 4; i++)
#pragma unroll
        for (int j = 0; j < 4; j++)
#pragma unroll
            for (int k = 0; k < 4; k++) acc[i][j][k] = 0.0f;

    uint2 rA[4], rB[4];

    auto ldg_tile = [&](int kb) {
#pragma unroll
        for (int j = 0; j < 4; j++) {
            int r = srow + 32 * j;
            float4 va = *(const float4*)(Aptr + (size_t)r * HDIM + kb + sc4);
            float4 vb = *(const float4*)(Bptr + (size_t)r * HDIM + kb + sc4);
            rA[j].x = pack_half2(va.x, va.y);
            rA[j].y = pack_half2(va.z, va.w);
            rB[j].x = pack_half2(vb.x, vb.y);
            rB[j].y = pack_half2(vb.z, vb.w);
        }
    };
    auto sts_tile = [&](int buf) {
#pragma unroll
        for (int j = 0; j < 4; j++) {
            int r = srow + 32 * j;
            *(uint2*)(&As[buf][r * PITCH + sc4]) = rA[j];
            *(uint2*)(&Bs[buf][r * PITCH + sc4]) = rB[j];
        }
    };

    ldg_tile(0);
    sts_tile(0);
    __syncthreads();

    int buf = 0;
    for (int kt = 0; kt < NKT; kt++) {
        if (kt + 1 < NKT) ldg_tile((kt + 1) * BK);

        // compute current tile: 2 k-steps of K=16
#pragma unroll
        for (int kk = 0; kk < 2; kk++) {
            uint32_t af[4][4], bf[4][2];
#pragma unroll
            for (int mt = 0; mt < 4; mt++) {
                const __half* p = &As[buf][(warpM * 64 + mt * 16 + grp) * PITCH
                                          + kk * 16 + 2 * qid];
                af[mt][0] = *(const uint32_t*)(p);
                af[mt][1] = *(const uint32_t*)(p + 8 * PITCH);
                af[mt][2] = *(const uint32_t*)(p + 8);
                af[mt][3] = *(const uint32_t*)(p + 8 * PITCH + 8);
            }
#pragma unroll
            for (int nt = 0; nt < 4; nt++) {
                const __half* p = &Bs[buf][(warpN * 32 + nt * 8 + grp) * PITCH
                                          + kk * 16 + 2 * qid];
                bf[nt][0] = *(const uint32_t*)(p);
                bf[nt][1] = *(const uint32_t*)(p + 8);
            }
#pragma unroll
            for (int mt = 0; mt < 4; mt++)
#pragma unroll
                for (int nt = 0; nt < 4; nt++)
                    mma_f16(acc[mt][nt][0], acc[mt][nt][1],
                            acc[mt][nt][2], acc[mt][nt][3],
                            af[mt][0], af[mt][1], af[mt][2], af[mt][3],
                            bf[nt][0], bf[nt][1]);
        }

        if (kt + 1 < NKT) {
            sts_tile(buf ^ 1);
            __syncthreads();
            buf ^= 1;
        }
    }

    if (MODE == 0) {
#pragma unroll
        for (int mt = 0; mt < 4; mt++) {
            int r0 = rowBase + warpM * 64 + mt * 16 + grp;
#pragma unroll
            for (int nt = 0; nt < 4; nt++) {
                int c0 = colBase + warpN * 32 + nt * 8 + qid * 2;
                g_wc[(size_t)r0 * HDIM + c0]           = acc[mt][nt][0];
                g_wc[(size_t)r0 * HDIM + c0 + 1]       = acc[mt][nt][1];
                g_wc[(size_t)(r0 + 8) * HDIM + c0]     = acc[mt][nt][2];
                g_wc[(size_t)(r0 + 8) * HDIM + c0 + 1] = acc[mt][nt][3];
            }
        }
    } else {
        float part[8];
#pragma unroll
        for (int i = 0; i < 8; i++) part[i] = 0.0f;

#pragma unroll
        for (int mt = 0; mt < 4; mt++) {
            int r0 = rowBase + warpM * 64 + mt * 16 + grp;
            int r1 = r0 + 8;
            int b0 = r0 & (BDIM - 1), s0 = r0 >> 13;
            int b1 = r1 & (BDIM - 1), s1 = r1 >> 13;
#pragma unroll
            for (int nt = 0; nt < 4; nt++) {
                int c0 = colBase + warpN * 32 + nt * 8 + qid * 2;
                float wt0 = Wt[c0], wt1 = Wt[c0 + 1];
                float e;
                e = fast_tanh(acc[mt][nt][0] + g_wc[(size_t)b0 * HDIM + c0]
                              + bias[s0 * HDIM + c0]);
                part[mt * 2] += e * wt0;
                e = fast_tanh(acc[mt][nt][1] + g_wc[(size_t)b0 * HDIM + c0 + 1]
                              + bias[s0 * HDIM + c0 + 1]);
                part[mt * 2] += e * wt1;
                e = fast_tanh(acc[mt][nt][2] + g_wc[(size_t)b1 * HDIM + c0]
                              + bias[s1 * HDIM + c0]);
                part[mt * 2 + 1] += e * wt0;
                e = fast_tanh(acc[mt][nt][3] + g_wc[(size_t)b1 * HDIM + c0 + 1]
                              + bias[s1 * HDIM + c0 + 1]);
                part[mt * 2 + 1] += e * wt1;
            }
        }
#pragma unroll
        for (int i = 0; i < 8; i++) {
            part[i] += __shfl_xor_sync(0xffffffffu, part[i], 1);
            part[i] += __shfl_xor_sync(0xffffffffu, part[i], 2);
        }
        if (qid == 0) {
#pragma unroll
            for (int mt = 0; mt < 4; mt++) {
                int r0 = rowBase + warpM * 64 + mt * 16 + grp;
                atomicAdd(&g_scores[r0],     part[mt * 2]);
                atomicAdd(&g_scores[r0 + 8], part[mt * 2 + 1]);
            }
        }
    }
}

// ---------------------------------------------------------------------------
// Per-b softmax over SEQ scores + weighted sum of allh rows -> out[b, :]
// 256 threads, each owns one float4 of the 1024-wide row.
// ---------------------------------------------------------------------------
__global__ __launch_bounds__(256)
void softmax_combine_kernel(const float* __restrict__ allh,
                            float* __restrict__ out)
{
    int b = blockIdx.x;
    __shared__ float s_alpha[32];

    if (threadIdx.x < 32) {
        int lane = threadIdx.x;
        float v = (lane < SEQ) ? g_scores[lane * BDIM + b] : -1e30f;
        float m = v;
#pragma unroll
        for (int o = 16; o > 0; o >>= 1)
            m = fmaxf(m, __shfl_xor_sync(0xffffffffu, m, o));
        float e = (lane < SEQ) ? __expf(v - m) : 0.0f;
        float sum = e;
#pragma unroll
        for (int o = 16; o > 0; o >>= 1)
            sum += __shfl_xor_sync(0xffffffffu, sum, o);
        s_alpha[lane] = e / sum;
    }
    __syncthreads();

    const float4* hb = (const float4*)(allh + (size_t)b * HDIM) + threadIdx.x;
    float4 accv = make_float4(0.f, 0.f, 0.f, 0.f);
#pragma unroll
    for (int s = 0; s < SEQ; s++) {
        float a = s_alpha[s];
        float4 v = hb[(size_t)s * BDIM * (HDIM / 4)];
        accv.x += a * v.x; accv.y += a * v.y;
        accv.z += a * v.z; accv.w += a * v.w;
    }
    ((float4*)(out + (size_t)b * HDIM))[threadIdx.x] = accv;
}

// ------------------------- launch -------------------------
extern "C" void kernel_launch(void* const* d_in, const int* in_sizes, int n_in,
                              void* d_out, int out_size)
{
    const float* c    = (const float*)d_in[0];  // [1, B, H]
    const float* allh = (const float*)d_in[1];  // [S, B, H]
    const float* W    = (const float*)d_in[2];  // [H, H]
    const float* V    = (const float*)d_in[3];  // [H, H]
    const float* bias = (const float*)d_in[4];  // [S, H]
    const float* Wt   = (const float*)d_in[5];  // [H, 1]
    float* out = (float*)d_out;                 // [1, B, H]
    (void)in_sizes; (void)n_in; (void)out_size;

    float* g_wt_p;  cudaGetSymbolAddress((void**)&g_wt_p, g_wt);
    float* g_vt_p;  cudaGetSymbolAddress((void**)&g_vt_p, g_vt);

    // 1) zero score accumulator; transpose weights to [n][k]
    zero_scores_kernel<<<MTOT / 256, 256>>>();
    transpose_kernel<<<dim3(32, 32), dim3(32, 8)>>>(W, g_wt_p);
    transpose_kernel<<<dim3(32, 32), dim3(32, 8)>>>(V, g_vt_p);

    // 2) wc = c @ W
    gemm_f16_kernel<0><<<dim3(HDIM / 128, BDIM / 128), 256>>>(
        c, g_wt_p, nullptr, nullptr);

    // 3) fused vh GEMM + tanh + score reduction
    gemm_f16_kernel<1><<<dim3(HDIM / 128, MTOT / 128), 256>>>(
        allh, g_vt_p, bias, Wt);

    // 4) softmax over S and weighted combine
    softmax_combine_kernel<<<BDIM, 256>>>(allh, out);
}

// round 4
// speedup vs baseline: 1.7832x; 1.3567x over previous
#include <cuda_runtime.h>
#include <cuda_fp16.h>
#include <cstdint>

#define SEQ   21
#define BDIM  8192
#define HDIM  1024
#define MTOT  (SEQ * BDIM)   // 172032

#define BM 128
#define BN 256
#define BK 32
#define NKT (HDIM / BK)      // 32
#define STAGES 3
#define PITCH 40                          // halves per smem row (80B, 16B-aligned)
#define A_BYTES (BM * PITCH * 2)          // 10240
#define B_BYTES (BN * PITCH * 2)          // 20480
#define STAGE_BYTES (A_BYTES + B_BYTES)   // 30720
#define SMEM_SIZE (STAGES * STAGE_BYTES)  // 92160

// ---- device scratch (allocation-free rule) ----
__device__ __half g_allh_h[(size_t)MTOT * HDIM];   // 352 MB fp16 copy of allh
__device__ __half g_c_h[(size_t)BDIM * HDIM];      // 16 MB fp16 copy of c
__device__ __half g_wt_h[(size_t)HDIM * HDIM];     // W^T fp16 [n][k]
__device__ __half g_vt_h[(size_t)HDIM * HDIM];     // V^T fp16 [n][k]
__device__ float  g_wc[(size_t)BDIM * HDIM];       // 32 MB: wc = c @ W (fp32)
__device__ float  g_scores[MTOT];

// ------------------------- helpers -------------------------
__device__ __forceinline__ uint32_t smem_u32(const void* p) {
    uint32_t a;
    asm("{ .reg .u64 t; cvta.to.shared.u64 t, %1; cvt.u32.u64 %0, t; }"
        : "=r"(a) : "l"(p));
    return a;
}
__device__ __forceinline__ float fast_tanh(float x) {
    float r; asm("tanh.approx.f32 %0, %1;" : "=f"(r) : "f"(x)); return r;
}
__device__ __forceinline__ uint32_t pack_half2(float lo, float hi) {
    uint32_t r;
    asm("cvt.rn.f16x2.f32 %0, %1, %2;" : "=r"(r) : "f"(hi), "f"(lo));
    return r;
}
__device__ __forceinline__ void cp_async16(uint32_t dst, const void* src) {
    asm volatile("cp.async.cg.shared.global [%0], [%1], 16;" :: "r"(dst), "l"(src));
}
__device__ __forceinline__ void cp_commit() {
    asm volatile("cp.async.commit_group;" ::: "memory");
}
template <int N>
__device__ __forceinline__ void cp_wait() {
    asm volatile("cp.async.wait_group %0;" :: "n"(N) : "memory");
}
__device__ __forceinline__ void ldsm4(uint32_t& r0, uint32_t& r1,
                                      uint32_t& r2, uint32_t& r3, uint32_t addr) {
    asm volatile("ldmatrix.sync.aligned.m8n8.x4.shared.b16 {%0,%1,%2,%3}, [%4];"
                 : "=r"(r0), "=r"(r1), "=r"(r2), "=r"(r3) : "r"(addr));
}
__device__ __forceinline__ void mma_f16(
    float& d0, float& d1, float& d2, float& d3,
    uint32_t a0, uint32_t a1, uint32_t a2, uint32_t a3,
    uint32_t b0, uint32_t b1)
{
    asm volatile(
        "mma.sync.aligned.m16n8k16.row.col.f32.f16.f16.f32 "
        "{%0,%1,%2,%3}, {%4,%5,%6,%7}, {%8,%9}, {%0,%1,%2,%3};\n"
        : "+f"(d0), "+f"(d1), "+f"(d2), "+f"(d3)
        : "r"(a0), "r"(a1), "r"(a2), "r"(a3), "r"(b0), "r"(b1));
}

// ------------------------- small kernels -------------------------
__global__ void zero_scores_kernel() {
    int i = blockIdx.x * blockDim.x + threadIdx.x;
    if (i < MTOT) g_scores[i] = 0.0f;
}

__global__ __launch_bounds__(256)
void f32_to_f16_kernel(const float* __restrict__ in, __half* __restrict__ out, int n4) {
    int i = blockIdx.x * blockDim.x + threadIdx.x;
    if (i < n4) {
        float4 v = ((const float4*)in)[i];
        uint2 o;
        o.x = pack_half2(v.x, v.y);
        o.y = pack_half2(v.z, v.w);
        ((uint2*)out)[i] = o;
    }
}

__global__ void transpose_f16_kernel(const float* __restrict__ in,
                                     __half* __restrict__ out) {
    __shared__ float t[32][33];
    int x = blockIdx.x * 32 + threadIdx.x;
#pragma unroll
    for (int i = 0; i < 32; i += 8) {
        int y = blockIdx.y * 32 + threadIdx.y + i;
        t[threadIdx.y + i][threadIdx.x] = in[(size_t)y * HDIM + x];
    }
    __syncthreads();
    int x2 = blockIdx.y * 32 + threadIdx.x;
#pragma unroll
    for (int i = 0; i < 32; i += 8) {
        int y2 = blockIdx.x * 32 + threadIdx.y + i;
        out[(size_t)y2 * HDIM + x2] = __float2half(t[threadIdx.x][threadIdx.y + i]);
    }
}

// ---------------------------------------------------------------------------
// FP16 GEMM (fp32 accum). CTA tile 128x256, BK=32, 3-stage cp.async pipeline.
// 8 warps (2M x 4N), warp tile 64x64, ldmatrix fragment loads.
//   A: [M][K] f16 row-major.  Bt: [N][K] f16 (transposed weight).
// MODE 0: C -> g_wc.
// MODE 1: e = tanh(C + wc[b,:] + bias[s,:]); scores[row] += e . Wt
// ---------------------------------------------------------------------------
template <int MODE>
__global__ __launch_bounds__(256, 1)
void gemm_f16_kernel(const __half* __restrict__ A,
                     const __half* __restrict__ Bt,
                     const float* __restrict__ bias,
                     const float* __restrict__ Wt)
{
    extern __shared__ __align__(16) char smem[];
    const uint32_t sbase = smem_u32(smem);

    const int tid   = threadIdx.x;
    const int lane  = tid & 31;
    const int wid   = tid >> 5;
    const int warpM = wid & 1;   // 0..1
    const int warpN = wid >> 1;  // 0..3
    const int grp   = lane >> 2; // 0..7
    const int qid   = lane & 3;  // 0..3

    const int m0 = blockIdx.y * BM;
    const int n0 = blockIdx.x * BN;
    const __half* Ab = A  + (size_t)m0 * HDIM;
    const __half* Bb = Bt + (size_t)n0 * HDIM;

    // precomputed ldmatrix lane offsets (bytes, within a stage)
    uint32_t aoff[4], boff[4];
#pragma unroll
    for (int mt = 0; mt < 4; mt++)
        aoff[mt] = (uint32_t)(((warpM * 64 + mt * 16 + (lane & 15)) * PITCH
                               + ((lane >> 4) * 8)) * 2);
#pragma unroll
    for (int n2 = 0; n2 < 4; n2++)
        boff[n2] = (uint32_t)(A_BYTES
                   + ((warpN * 64 + n2 * 16 + (lane & 7) + (((lane >> 4) & 1) * 8)) * PITCH
                      + (((lane >> 3) & 1) * 8)) * 2);

    float acc[4][8][4];
#pragma unroll
    for (int i = 0; i < 4; i++)
#pragma unroll
        for (int j = 0; j < 8; j++)
#pragma unroll
            for (int k = 0; k < 4; k++) acc[i][j][k] = 0.0f;

    auto issue_tile = [&](int kt) {
        if (kt < NKT) {
            uint32_t soff = sbase + (uint32_t)(kt % STAGES) * STAGE_BYTES;
            int kb = kt * BK;
#pragma unroll
            for (int i = 0; i < 2; i++) {           // A: 512 16B chunks
                int id = tid + 256 * i;
                int r = id >> 2, cc = id & 3;
                cp_async16(soff + (uint32_t)((r * PITCH + cc * 8) * 2),
                           Ab + (size_t)r * HDIM + kb + cc * 8);
            }
#pragma unroll
            for (int i = 0; i < 4; i++) {           // B: 1024 16B chunks
                int id = tid + 256 * i;
                int r = id >> 2, cc = id & 3;
                cp_async16(soff + A_BYTES + (uint32_t)((r * PITCH + cc * 8) * 2),
                           Bb + (size_t)r * HDIM + kb + cc * 8);
            }
        }
        cp_commit();
    };

    issue_tile(0);
    issue_tile(1);

    for (int kt = 0; kt < NKT; kt++) {
        cp_wait<STAGES - 2>();
        __syncthreads();
        issue_tile(kt + STAGES - 1);

        const uint32_t buf = sbase + (uint32_t)(kt % STAGES) * STAGE_BYTES;
#pragma unroll
        for (int kk = 0; kk < 2; kk++) {
            uint32_t af[4][4], bf[8][2];
#pragma unroll
            for (int mt = 0; mt < 4; mt++)
                ldsm4(af[mt][0], af[mt][1], af[mt][2], af[mt][3],
                      buf + aoff[mt] + kk * 32);
#pragma unroll
            for (int n2 = 0; n2 < 4; n2++)
                ldsm4(bf[2 * n2][0], bf[2 * n2][1], bf[2 * n2 + 1][0], bf[2 * n2 + 1][1],
                      buf + boff[n2] + kk * 32);
#pragma unroll
            for (int mt = 0; mt < 4; mt++)
#pragma unroll
                for (int nt = 0; nt < 8; nt++)
                    mma_f16(acc[mt][nt][0], acc[mt][nt][1],
                            acc[mt][nt][2], acc[mt][nt][3],
                            af[mt][0], af[mt][1], af[mt][2], af[mt][3],
                            bf[nt][0], bf[nt][1]);
        }
    }

    if (MODE == 0) {
#pragma unroll
        for (int mt = 0; mt < 4; mt++) {
            int r0 = m0 + warpM * 64 + mt * 16 + grp;
#pragma unroll
            for (int nt = 0; nt < 8; nt++) {
                int c0 = n0 + warpN * 64 + nt * 8 + qid * 2;
                *(float2*)&g_wc[(size_t)r0 * HDIM + c0] =
                    make_float2(acc[mt][nt][0], acc[mt][nt][1]);
                *(float2*)&g_wc[(size_t)(r0 + 8) * HDIM + c0] =
                    make_float2(acc[mt][nt][2], acc[mt][nt][3]);
            }
        }
    } else {
        float part[8];
#pragma unroll
        for (int i = 0; i < 8; i++) part[i] = 0.0f;

        const float* biasrow = bias + (size_t)(m0 >> 13) * HDIM;  // s const per CTA
        const int bbase = m0 & (BDIM - 1);

#pragma unroll
        for (int nt = 0; nt < 8; nt++) {
            int c0 = n0 + warpN * 64 + nt * 8 + qid * 2;
            float2 wt2 = *(const float2*)&Wt[c0];
            float2 bi2 = *(const float2*)&biasrow[c0];
#pragma unroll
            for (int mt = 0; mt < 4; mt++) {
                int b0 = bbase + warpM * 64 + mt * 16 + grp;
                float2 w0 = *(const float2*)&g_wc[(size_t)b0 * HDIM + c0];
                float2 w1 = *(const float2*)&g_wc[(size_t)(b0 + 8) * HDIM + c0];
                part[mt * 2] += fast_tanh(acc[mt][nt][0] + w0.x + bi2.x) * wt2.x
                              + fast_tanh(acc[mt][nt][1] + w0.y + bi2.y) * wt2.y;
                part[mt * 2 + 1] += fast_tanh(acc[mt][nt][2] + w1.x + bi2.x) * wt2.x
                                  + fast_tanh(acc[mt][nt][3] + w1.y + bi2.y) * wt2.y;
            }
        }
#pragma unroll
        for (int i = 0; i < 8; i++) {
            part[i] += __shfl_xor_sync(0xffffffffu, part[i], 1);
            part[i] += __shfl_xor_sync(0xffffffffu, part[i], 2);
        }
        if (qid == 0) {
#pragma unroll
            for (int mt = 0; mt < 4; mt++) {
                int r0 = m0 + warpM * 64 + mt * 16 + grp;
                atomicAdd(&g_scores[r0],     part[mt * 2]);
                atomicAdd(&g_scores[r0 + 8], part[mt * 2 + 1]);
            }
        }
    }
}

// ---------------------------------------------------------------------------
// Per-b softmax over SEQ scores + weighted sum of fp16 allh rows -> out[b, :]
// ---------------------------------------------------------------------------
__global__ __launch_bounds__(256)
void softmax_combine_kernel(float* __restrict__ out)
{
    int b = blockIdx.x;
    __shared__ float s_alpha[32];

    if (threadIdx.x < 32) {
        int lane = threadIdx.x;
        float v = (lane < SEQ) ? g_scores[lane * BDIM + b] : -1e30f;
        float m = v;
#pragma unroll
        for (int o = 16; o > 0; o >>= 1)
            m = fmaxf(m, __shfl_xor_sync(0xffffffffu, m, o));
        float e = (lane < SEQ) ? __expf(v - m) : 0.0f;
        float sum = e;
#pragma unroll
        for (int o = 16; o > 0; o >>= 1)
            sum += __shfl_xor_sync(0xffffffffu, sum, o);
        s_alpha[lane] = e / sum;
    }
    __syncthreads();

    const uint2* hb = (const uint2*)(g_allh_h + (size_t)b * HDIM) + threadIdx.x;
    float4 accv = make_float4(0.f, 0.f, 0.f, 0.f);
#pragma unroll
    for (int s = 0; s < SEQ; s++) {
        float a = s_alpha[s];
        uint2 v = hb[(size_t)s * (BDIM * HDIM / 4)];
        float2 f0 = __half22float2(*(__half2*)&v.x);
        float2 f1 = __half22float2(*(__half2*)&v.y);
        accv.x += a * f0.x; accv.y += a * f0.y;
        accv.z += a * f1.x; accv.w += a * f1.y;
    }
    ((float4*)(out + (size_t)b * HDIM))[threadIdx.x] = accv;
}

// ------------------------- launch -------------------------
extern "C" void kernel_launch(void* const* d_in, const int* in_sizes, int n_in,
                              void* d_out, int out_size)
{
    const float* c    = (const float*)d_in[0];  // [1, B, H]
    const float* allh = (const float*)d_in[1];  // [S, B, H]
    const float* W    = (const float*)d_in[2];  // [H, H]
    const float* V    = (const float*)d_in[3];  // [H, H]
    const float* bias = (const float*)d_in[4];  // [S, H]
    const float* Wt   = (const float*)d_in[5];  // [H, 1]
    float* out = (float*)d_out;                 // [1, B, H]
    (void)in_sizes; (void)n_in; (void)out_size;

    static bool attr_set = false;
    if (!attr_set) {
        cudaFuncSetAttribute(gemm_f16_kernel<0>,
                             cudaFuncAttributeMaxDynamicSharedMemorySize, SMEM_SIZE);
        cudaFuncSetAttribute(gemm_f16_kernel<1>,
                             cudaFuncAttributeMaxDynamicSharedMemorySize, SMEM_SIZE);
        attr_set = true;
    }

    __half* c_h;    cudaGetSymbolAddress((void**)&c_h,    g_c_h);
    __half* allh_h; cudaGetSymbolAddress((void**)&allh_h, g_allh_h);
    __half* wt_h;   cudaGetSymbolAddress((void**)&wt_h,   g_wt_h);
    __half* vt_h;   cudaGetSymbolAddress((void**)&vt_h,   g_vt_h);

    // 1) housekeeping + fp16 conversions
    zero_scores_kernel<<<MTOT / 256, 256>>>();
    transpose_f16_kernel<<<dim3(32, 32), dim3(32, 8)>>>(W, wt_h);
    transpose_f16_kernel<<<dim3(32, 32), dim3(32, 8)>>>(V, vt_h);
    f32_to_f16_kernel<<<(BDIM * HDIM / 4) / 256, 256>>>(c, c_h, BDIM * HDIM / 4);
    f32_to_f16_kernel<<<((size_t)MTOT * HDIM / 4) / 256, 256>>>(
        allh, allh_h, (int)((size_t)MTOT * HDIM / 4));

    // 2) wc = c @ W
    gemm_f16_kernel<0><<<dim3(HDIM / BN, BDIM / BM), 256, SMEM_SIZE>>>(
        c_h, wt_h, nullptr, nullptr);

    // 3) fused vh GEMM + tanh + score reduction
    gemm_f16_kernel<1><<<dim3(HDIM / BN, MTOT / BM), 256, SMEM_SIZE>>>(
        allh_h, vt_h, bias, Wt);

    // 4) softmax over S and weighted combine
    softmax_combine_kernel<<<BDIM, 256>>>(out);
}

// round 5
// speedup vs baseline: 1.9042x; 1.0678x over previous
#include <cuda_runtime.h>
#include <cuda_fp16.h>
#include <cstdint>

#define SEQ   21
#define BDIM  8192
#define HDIM  1024
#define MTOT  (SEQ * BDIM)   // 172032

#define BM 128
#define BN 128
#define BK 32
#define NKT (HDIM / BK)      // 32
#define STAGES 4
#define PITCH 40                          // halves per smem row (80B)
#define A_BYTES (BM * PITCH * 2)          // 10240
#define B_BYTES (BN * PITCH * 2)          // 10240
#define STAGE_BYTES (A_BYTES + B_BYTES)   // 20480
#define SMEM_SIZE (STAGES * STAGE_BYTES)  // 81920

// ---- device scratch (allocation-free rule) ----
__device__ __half g_allh_h[(size_t)MTOT * HDIM];   // 352 MB fp16 copy of allh
__device__ __half g_c_h[(size_t)BDIM * HDIM];      // 16 MB fp16 copy of c
__device__ __half g_wt_h[(size_t)HDIM * HDIM];     // W^T fp16 [n][k]
__device__ __half g_vt_h[(size_t)HDIM * HDIM];     // V^T fp16 [n][k]
__device__ float  g_wc[(size_t)BDIM * HDIM];       // 32 MB: wc = c @ W (fp32)
__device__ float  g_scores[MTOT];

// ------------------------- helpers -------------------------
__device__ __forceinline__ uint32_t smem_u32(const void* p) {
    uint32_t a;
    asm("{ .reg .u64 t; cvta.to.shared.u64 t, %1; cvt.u32.u64 %0, t; }"
        : "=r"(a) : "l"(p));
    return a;
}
__device__ __forceinline__ float fast_tanh(float x) {
    float r; asm("tanh.approx.f32 %0, %1;" : "=f"(r) : "f"(x)); return r;
}
__device__ __forceinline__ uint32_t pack_half2(float lo, float hi) {
    uint32_t r;
    asm("cvt.rn.f16x2.f32 %0, %1, %2;" : "=r"(r) : "f"(hi), "f"(lo));
    return r;
}
__device__ __forceinline__ void cp_async16(uint32_t dst, const void* src) {
    asm volatile("cp.async.cg.shared.global [%0], [%1], 16;" :: "r"(dst), "l"(src));
}
__device__ __forceinline__ void cp_commit() {
    asm volatile("cp.async.commit_group;" ::: "memory");
}
template <int N>
__device__ __forceinline__ void cp_wait() {
    asm volatile("cp.async.wait_group %0;" :: "n"(N) : "memory");
}
__device__ __forceinline__ void ldsm4(uint32_t& r0, uint32_t& r1,
                                      uint32_t& r2, uint32_t& r3, uint32_t addr) {
    asm volatile("ldmatrix.sync.aligned.m8n8.x4.shared.b16 {%0,%1,%2,%3}, [%4];"
                 : "=r"(r0), "=r"(r1), "=r"(r2), "=r"(r3) : "r"(addr));
}
__device__ __forceinline__ void mma_f16(
    float& d0, float& d1, float& d2, float& d3,
    uint32_t a0, uint32_t a1, uint32_t a2, uint32_t a3,
    uint32_t b0, uint32_t b1)
{
    asm volatile(
        "mma.sync.aligned.m16n8k16.row.col.f32.f16.f16.f32 "
        "{%0,%1,%2,%3}, {%4,%5,%6,%7}, {%8,%9}, {%0,%1,%2,%3};\n"
        : "+f"(d0), "+f"(d1), "+f"(d2), "+f"(d3)
        : "r"(a0), "r"(a1), "r"(a2), "r"(a3), "r"(b0), "r"(b1));
}

// ------------------------- small kernels -------------------------
__global__ void zero_scores_kernel() {
    int i = blockIdx.x * blockDim.x + threadIdx.x;
    if (i < MTOT) g_scores[i] = 0.0f;
}

// 4 float4 per thread per trip, grid-stride, for DRAM saturation
__global__ __launch_bounds__(256)
void f32_to_f16_kernel(const float* __restrict__ in, __half* __restrict__ out,
                       long long n4) {
    long long stride = (long long)gridDim.x * 1024;     // 256 thr * 4 vec
    for (long long base = (long long)blockIdx.x * 1024 + threadIdx.x * 4;
         base < n4; base += stride) {
        float4 v0 = ((const float4*)in)[base + 0];
        float4 v1 = ((const float4*)in)[base + 1];
        float4 v2 = ((const float4*)in)[base + 2];
        float4 v3 = ((const float4*)in)[base + 3];
        uint2 o0, o1, o2, o3;
        o0.x = pack_half2(v0.x, v0.y); o0.y = pack_half2(v0.z, v0.w);
        o1.x = pack_half2(v1.x, v1.y); o1.y = pack_half2(v1.z, v1.w);
        o2.x = pack_half2(v2.x, v2.y); o2.y = pack_half2(v2.z, v2.w);
        o3.x = pack_half2(v3.x, v3.y); o3.y = pack_half2(v3.z, v3.w);
        ((uint2*)out)[base + 0] = o0;
        ((uint2*)out)[base + 1] = o1;
        ((uint2*)out)[base + 2] = o2;
        ((uint2*)out)[base + 3] = o3;
    }
}

__global__ void transpose_f16_kernel(const float* __restrict__ in,
                                     __half* __restrict__ out) {
    __shared__ float t[32][33];
    int x = blockIdx.x * 32 + threadIdx.x;
#pragma unroll
    for (int i = 0; i < 32; i += 8) {
        int y = blockIdx.y * 32 + threadIdx.y + i;
        t[threadIdx.y + i][threadIdx.x] = in[(size_t)y * HDIM + x];
    }
    __syncthreads();
    int x2 = blockIdx.y * 32 + threadIdx.x;
#pragma unroll
    for (int i = 0; i < 32; i += 8) {
        int y2 = blockIdx.x * 32 + threadIdx.y + i;
        out[(size_t)y2 * HDIM + x2] = __float2half(t[threadIdx.x][threadIdx.y + i]);
    }
}

// ---------------------------------------------------------------------------
// FP16 GEMM (fp32 accum). CTA tile 128x128, BK=32, 4-stage cp.async pipeline,
// 2 CTAs/SM. 8 warps (2M x 4N), warp tile 64x32, ldmatrix fragments.
//   A: [M][K] f16 row-major.  Bt: [N][K] f16 (transposed weight).
// Grid: (n_tiles, s, b_tiles); m0 = s*BDIM + bt*BM.
// MODE 0: C -> g_wc.
// MODE 1: e = tanh(C + wc[b,:] + bias[s,:]); scores[row] += e . Wt
// ---------------------------------------------------------------------------
template <int MODE>
__global__ __launch_bounds__(256, 2)
void gemm_f16_kernel(const __half* __restrict__ A,
                     const __half* __restrict__ Bt,
                     const float* __restrict__ bias,
                     const float* __restrict__ Wt)
{
    extern __shared__ __align__(16) char smem[];
    const uint32_t sbase = smem_u32(smem);

    const int tid   = threadIdx.x;
    const int lane  = tid & 31;
    const int wid   = tid >> 5;
    const int warpM = wid & 1;   // 0..1  (64-row bands)
    const int warpN = wid >> 1;  // 0..3  (32-col bands)
    const int grp   = lane >> 2; // 0..7
    const int qid   = lane & 3;  // 0..3

    const int m0 = blockIdx.y * BDIM + blockIdx.z * BM;
    const int n0 = blockIdx.x * BN;
    const __half* Ab = A  + (size_t)m0 * HDIM;
    const __half* Bb = Bt + (size_t)n0 * HDIM;

    // ldmatrix lane offsets (bytes within a stage)
    uint32_t aoff[4], boff[2];
#pragma unroll
    for (int mt = 0; mt < 4; mt++)
        aoff[mt] = (uint32_t)(((warpM * 64 + mt * 16 + (lane & 15)) * PITCH
                               + ((lane >> 4) * 8)) * 2);
#pragma unroll
    for (int n2 = 0; n2 < 2; n2++)
        boff[n2] = (uint32_t)(A_BYTES
                   + ((warpN * 32 + n2 * 16 + (lane & 7) + (((lane >> 4) & 1) * 8)) * PITCH
                      + (((lane >> 3) & 1) * 8)) * 2);

    float acc[4][4][4];
#pragma unroll
    for (int i = 0; i < 4; i++)
#pragma unroll
        for (int j = 0; j < 4; j++)
#pragma unroll
            for (int k = 0; k < 4; k++) acc[i][j][k] = 0.0f;

    // staging: A 512 chunks + B 512 chunks of 16B, 256 threads -> 2+2 each
    auto issue_tile = [&](int kt) {
        if (kt < NKT) {
            uint32_t soff = sbase + (uint32_t)(kt % STAGES) * STAGE_BYTES;
            int kb = kt * BK;
            int r = tid >> 1, cc = tid & 1;
#pragma unroll
            for (int half = 0; half < 2; half++) {   // A rows r, r+... : 2 chunks
                cp_async16(soff + (uint32_t)((r * PITCH + (cc * 2 + half) * 8) * 2),
                           Ab + (size_t)r * HDIM + kb + (cc * 2 + half) * 8);
            }
#pragma unroll
            for (int half = 0; half < 2; half++) {
                cp_async16(soff + A_BYTES + (uint32_t)((r * PITCH + (cc * 2 + half) * 8) * 2),
                           Bb + (size_t)r * HDIM + kb + (cc * 2 + half) * 8);
            }
        }
        cp_commit();
    };

    issue_tile(0);
    issue_tile(1);
    issue_tile(2);

    for (int kt = 0; kt < NKT; kt++) {
        cp_wait<STAGES - 2>();
        __syncthreads();
        issue_tile(kt + STAGES - 1);

        const uint32_t buf = sbase + (uint32_t)(kt % STAGES) * STAGE_BYTES;
#pragma unroll
        for (int kk = 0; kk < 2; kk++) {
            uint32_t af[4][4], bf[4][2];
#pragma unroll
            for (int mt = 0; mt < 4; mt++)
                ldsm4(af[mt][0], af[mt][1], af[mt][2], af[mt][3],
                      buf + aoff[mt] + kk * 32);
#pragma unroll
            for (int n2 = 0; n2 < 2; n2++)
                ldsm4(bf[2 * n2][0], bf[2 * n2][1], bf[2 * n2 + 1][0], bf[2 * n2 + 1][1],
                      buf + boff[n2] + kk * 32);
#pragma unroll
            for (int mt = 0; mt < 4; mt++)
#pragma unroll
                for (int nt = 0; nt < 4; nt++)
                    mma_f16(acc[mt][nt][0], acc[mt][nt][1],
                            acc[mt][nt][2], acc[mt][nt][3],
                            af[mt][0], af[mt][1], af[mt][2], af[mt][3],
                            bf[nt][0], bf[nt][1]);
        }
    }

    if (MODE == 0) {
#pragma unroll
        for (int mt = 0; mt < 4; mt++) {
            int r0 = m0 + warpM * 64 + mt * 16 + grp;
#pragma unroll
            for (int nt = 0; nt < 4; nt++) {
                int c0 = n0 + warpN * 32 + nt * 8 + qid * 2;
                *(float2*)&g_wc[(size_t)r0 * HDIM + c0] =
                    make_float2(acc[mt][nt][0], acc[mt][nt][1]);
                *(float2*)&g_wc[(size_t)(r0 + 8) * HDIM + c0] =
                    make_float2(acc[mt][nt][2], acc[mt][nt][3]);
            }
        }
    } else {
        float part[8];
#pragma unroll
        for (int i = 0; i < 8; i++) part[i] = 0.0f;

        const float* biasrow = bias + (size_t)blockIdx.y * HDIM;
        const int bbase = blockIdx.z * BM;

#pragma unroll
        for (int nt = 0; nt < 4; nt++) {
            int c0 = n0 + warpN * 32 + nt * 8 + qid * 2;
            float2 wt2 = *(const float2*)&Wt[c0];
            float2 bi2 = *(const float2*)&biasrow[c0];
#pragma unroll
            for (int mt = 0; mt < 4; mt++) {
                int b0 = bbase + warpM * 64 + mt * 16 + grp;
                float2 w0 = *(const float2*)&g_wc[(size_t)b0 * HDIM + c0];
                float2 w1 = *(const float2*)&g_wc[(size_t)(b0 + 8) * HDIM + c0];
                part[mt * 2]     += fast_tanh(acc[mt][nt][0] + w0.x + bi2.x) * wt2.x
                                  + fast_tanh(acc[mt][nt][1] + w0.y + bi2.y) * wt2.y;
                part[mt * 2 + 1] += fast_tanh(acc[mt][nt][2] + w1.x + bi2.x) * wt2.x
                                  + fast_tanh(acc[mt][nt][3] + w1.y + bi2.y) * wt2.y;
            }
        }
#pragma unroll
        for (int i = 0; i < 8; i++) {
            part[i] += __shfl_xor_sync(0xffffffffu, part[i], 1);
            part[i] += __shfl_xor_sync(0xffffffffu, part[i], 2);
        }
        if (qid == 0) {
#pragma unroll
            for (int mt = 0; mt < 4; mt++) {
                int r0 = m0 + warpM * 64 + mt * 16 + grp;
                atomicAdd(&g_scores[r0],     part[mt * 2]);
                atomicAdd(&g_scores[r0 + 8], part[mt * 2 + 1]);
            }
        }
    }
}

// ---------------------------------------------------------------------------
// Per-b softmax over SEQ scores + weighted sum of fp16 allh rows -> out[b, :]
// ---------------------------------------------------------------------------
__global__ __launch_bounds__(256)
void softmax_combine_kernel(float* __restrict__ out)
{
    int b = blockIdx.x;
    __shared__ float s_alpha[32];

    if (threadIdx.x < 32) {
        int lane = threadIdx.x;
        float v = (lane < SEQ) ? g_scores[lane * BDIM + b] : -1e30f;
        float m = v;
#pragma unroll
        for (int o = 16; o > 0; o >>= 1)
            m = fmaxf(m, __shfl_xor_sync(0xffffffffu, m, o));
        float e = (lane < SEQ) ? __expf(v - m) : 0.0f;
        float sum = e;
#pragma unroll
        for (int o = 16; o > 0; o >>= 1)
            sum += __shfl_xor_sync(0xffffffffu, sum, o);
        s_alpha[lane] = e / sum;
    }
    __syncthreads();

    const uint2* hb = (const uint2*)(g_allh_h + (size_t)b * HDIM) + threadIdx.x;
    float4 accv = make_float4(0.f, 0.f, 0.f, 0.f);
#pragma unroll
    for (int s = 0; s < SEQ; s++) {
        float a = s_alpha[s];
        uint2 v = hb[(size_t)s * (BDIM * HDIM / 4)];
        float2 f0 = __half22float2(*(__half2*)&v.x);
        float2 f1 = __half22float2(*(__half2*)&v.y);
        accv.x += a * f0.x; accv.y += a * f0.y;
        accv.z += a * f1.x; accv.w += a * f1.y;
    }
    ((float4*)(out + (size_t)b * HDIM))[threadIdx.x] = accv;
}

// ------------------------- launch -------------------------
extern "C" void kernel_launch(void* const* d_in, const int* in_sizes, int n_in,
                              void* d_out, int out_size)
{
    const float* c    = (const float*)d_in[0];  // [1, B, H]
    const float* allh = (const float*)d_in[1];  // [S, B, H]
    const float* W    = (const float*)d_in[2];  // [H, H]
    const float* V    = (const float*)d_in[3];  // [H, H]
    const float* bias = (const float*)d_in[4];  // [S, H]
    const float* Wt   = (const float*)d_in[5];  // [H, 1]
    float* out = (float*)d_out;                 // [1, B, H]
    (void)in_sizes; (void)n_in; (void)out_size;

    static bool attr_set = false;
    if (!attr_set) {
        cudaFuncSetAttribute(gemm_f16_kernel<0>,
                             cudaFuncAttributeMaxDynamicSharedMemorySize, SMEM_SIZE);
        cudaFuncSetAttribute(gemm_f16_kernel<1>,
                             cudaFuncAttributeMaxDynamicSharedMemorySize, SMEM_SIZE);
        attr_set = true;
    }

    __half* c_h;    cudaGetSymbolAddress((void**)&c_h,    g_c_h);
    __half* allh_h; cudaGetSymbolAddress((void**)&allh_h, g_allh_h);
    __half* wt_h;   cudaGetSymbolAddress((void**)&wt_h,   g_wt_h);
    __half* vt_h;   cudaGetSymbolAddress((void**)&vt_h,   g_vt_h);

    // 1) housekeeping + fp16 conversions
    zero_scores_kernel<<<MTOT / 256, 256>>>();
    transpose_f16_kernel<<<dim3(32, 32), dim3(32, 8)>>>(W, wt_h);
    transpose_f16_kernel<<<dim3(32, 32), dim3(32, 8)>>>(V, vt_h);
    f32_to_f16_kernel<<<2048, 256>>>(c, c_h, (long long)BDIM * HDIM / 4);
    f32_to_f16_kernel<<<8192, 256>>>(allh, allh_h, (long long)MTOT * HDIM / 4);

    // 2) wc = c @ W   (grid: n-tiles x 1 x b-tiles)
    gemm_f16_kernel<0><<<dim3(HDIM / BN, 1, BDIM / BM), 256, SMEM_SIZE>>>(
        c_h, wt_h, nullptr, nullptr);

    // 3) fused vh GEMM + tanh + score reduction (grid: n-tiles x s x b-tiles)
    gemm_f16_kernel<1><<<dim3(HDIM / BN, SEQ, BDIM / BM), 256, SMEM_SIZE>>>(
        allh_h, vt_h, bias, Wt);

    // 4) softmax over S and weighted combine
    softmax_combine_kernel<<<BDIM, 256>>>(out);
}

// round 6
// speedup vs baseline: 2.2426x; 1.1777x over previous
#include <cuda_runtime.h>
#include <cuda_fp16.h>
#include <cstdint>

#define SEQ   21
#define BDIM  8192
#define HDIM  1024
#define MTOT  (SEQ * BDIM)   // 172032

#define BM 128
#define BN 128
#define BK 32
#define NKT (HDIM / BK)      // 32
#define STAGES 4
#define PITCH 40                          // halves per smem row (80B)
#define A_BYTES (BM * PITCH * 2)          // 10240
#define B_BYTES (BN * PITCH * 2)          // 10240
#define STAGE_BYTES (A_BYTES + B_BYTES)   // 20480
#define SMEM_SIZE (STAGES * STAGE_BYTES)  // 81920

// ---- device scratch (allocation-free rule) ----
__device__ __half g_allh_h[(size_t)MTOT * HDIM];   // 352 MB fp16 copy of allh
__device__ __half g_c_h[(size_t)BDIM * HDIM];      // 16 MB fp16 copy of c
__device__ __half g_wt_h[(size_t)HDIM * HDIM];     // W^T fp16 [n][k]
__device__ __half g_vt_h[(size_t)HDIM * HDIM];     // V^T fp16 [n][k]
__device__ float  g_wc[(size_t)BDIM * HDIM];       // 32 MB: wc = c @ W (fp32)
__device__ float  g_scores[MTOT];

// ------------------------- helpers -------------------------
__device__ __forceinline__ uint32_t smem_u32(const void* p) {
    uint32_t a;
    asm("{ .reg .u64 t; cvta.to.shared.u64 t, %1; cvt.u32.u64 %0, t; }"
        : "=r"(a) : "l"(p));
    return a;
}
__device__ __forceinline__ float fast_tanh(float x) {
    float r; asm("tanh.approx.f32 %0, %1;" : "=f"(r) : "f"(x)); return r;
}
__device__ __forceinline__ uint32_t pack_half2(float lo, float hi) {
    uint32_t r;
    asm("cvt.rn.f16x2.f32 %0, %1, %2;" : "=r"(r) : "f"(hi), "f"(lo));
    return r;
}
__device__ __forceinline__ void cp_async16(uint32_t dst, const void* src) {
    asm volatile("cp.async.cg.shared.global [%0], [%1], 16;" :: "r"(dst), "l"(src));
}
__device__ __forceinline__ void cp_commit() {
    asm volatile("cp.async.commit_group;" ::: "memory");
}
template <int N>
__device__ __forceinline__ void cp_wait() {
    asm volatile("cp.async.wait_group %0;" :: "n"(N) : "memory");
}
__device__ __forceinline__ void ldsm4(uint32_t& r0, uint32_t& r1,
                                      uint32_t& r2, uint32_t& r3, uint32_t addr) {
    asm volatile("ldmatrix.sync.aligned.m8n8.x4.shared.b16 {%0,%1,%2,%3}, [%4];"
                 : "=r"(r0), "=r"(r1), "=r"(r2), "=r"(r3) : "r"(addr));
}
__device__ __forceinline__ void mma_f16(
    float& d0, float& d1, float& d2, float& d3,
    uint32_t a0, uint32_t a1, uint32_t a2, uint32_t a3,
    uint32_t b0, uint32_t b1)
{
    asm volatile(
        "mma.sync.aligned.m16n8k16.row.col.f32.f16.f16.f32 "
        "{%0,%1,%2,%3}, {%4,%5,%6,%7}, {%8,%9}, {%0,%1,%2,%3};\n"
        : "+f"(d0), "+f"(d1), "+f"(d2), "+f"(d3)
        : "r"(a0), "r"(a1), "r"(a2), "r"(a3), "r"(b0), "r"(b1));
}

// ------------------------- small kernels -------------------------
__global__ void zero_scores_kernel() {
    int i = blockIdx.x * blockDim.x + threadIdx.x;
    if (i < MTOT) g_scores[i] = 0.0f;
}

__global__ __launch_bounds__(256)
void f32_to_f16_kernel(const float* __restrict__ in, __half* __restrict__ out,
                       long long n4) {
    long long stride = (long long)gridDim.x * 1024;     // 256 thr * 4 vec
    for (long long base = (long long)blockIdx.x * 1024 + threadIdx.x * 4;
         base < n4; base += stride) {
        float4 v0 = ((const float4*)in)[base + 0];
        float4 v1 = ((const float4*)in)[base + 1];
        float4 v2 = ((const float4*)in)[base + 2];
        float4 v3 = ((const float4*)in)[base + 3];
        uint2 o0, o1, o2, o3;
        o0.x = pack_half2(v0.x, v0.y); o0.y = pack_half2(v0.z, v0.w);
        o1.x = pack_half2(v1.x, v1.y); o1.y = pack_half2(v1.z, v1.w);
        o2.x = pack_half2(v2.x, v2.y); o2.y = pack_half2(v2.z, v2.w);
        o3.x = pack_half2(v3.x, v3.y); o3.y = pack_half2(v3.z, v3.w);
        ((uint2*)out)[base + 0] = o0;
        ((uint2*)out)[base + 1] = o1;
        ((uint2*)out)[base + 2] = o2;
        ((uint2*)out)[base + 3] = o3;
    }
}

__global__ void transpose_f16_kernel(const float* __restrict__ in,
                                     __half* __restrict__ out) {
    __shared__ float t[32][33];
    int x = blockIdx.x * 32 + threadIdx.x;
#pragma unroll
    for (int i = 0; i < 32; i += 8) {
        int y = blockIdx.y * 32 + threadIdx.y + i;
        t[threadIdx.y + i][threadIdx.x] = in[(size_t)y * HDIM + x];
    }
    __syncthreads();
    int x2 = blockIdx.y * 32 + threadIdx.x;
#pragma unroll
    for (int i = 0; i < 32; i += 8) {
        int y2 = blockIdx.x * 32 + threadIdx.y + i;
        out[(size_t)y2 * HDIM + x2] = __float2half(t[threadIdx.x][threadIdx.y + i]);
    }
}

// ---------------------------------------------------------------------------
// FP16 GEMM (fp32 accum). CTA tile 128x128, BK=32, 4-stage cp.async pipeline,
// 4 warps (2M x 2N), warp tile 64x64 -> high register reuse, 2 CTAs/SM.
//   A: [M][K] f16 row-major.  Bt: [N][K] f16 (transposed weight).
// Grid: (n_tiles, s, b_tiles); m0 = s*BDIM + bt*BM.
// MODE 0: C -> g_wc.
// MODE 1: e = tanh(C + wc[b,:] + bias[s,:]); scores[row] += e . Wt
// ---------------------------------------------------------------------------
template <int MODE>
__global__ __launch_bounds__(128, 2)
void gemm_f16_kernel(const __half* __restrict__ A,
                     const __half* __restrict__ Bt,
                     const float* __restrict__ bias,
                     const float* __restrict__ Wt)
{
    extern __shared__ __align__(16) char smem[];
    const uint32_t sbase = smem_u32(smem);

    const int tid   = threadIdx.x;
    const int lane  = tid & 31;
    const int wid   = tid >> 5;
    const int warpM = wid & 1;   // 0..1  (64-row bands)
    const int warpN = wid >> 1;  // 0..1  (64-col bands)
    const int grp   = lane >> 2; // 0..7
    const int qid   = lane & 3;  // 0..3

    const int m0 = blockIdx.y * BDIM + blockIdx.z * BM;
    const int n0 = blockIdx.x * BN;
    const __half* Ab = A  + (size_t)m0 * HDIM;
    const __half* Bb = Bt + (size_t)n0 * HDIM;

    // ldmatrix lane offsets (bytes within a stage)
    uint32_t aoff[4], boff[4];
#pragma unroll
    for (int mt = 0; mt < 4; mt++)
        aoff[mt] = (uint32_t)(((warpM * 64 + mt * 16 + (lane & 15)) * PITCH
                               + ((lane >> 4) * 8)) * 2);
#pragma unroll
    for (int n2 = 0; n2 < 4; n2++)
        boff[n2] = (uint32_t)(A_BYTES
                   + ((warpN * 64 + n2 * 16 + (lane & 7) + (((lane >> 4) & 1) * 8)) * PITCH
                      + (((lane >> 3) & 1) * 8)) * 2);

    float acc[4][8][4];
#pragma unroll
    for (int i = 0; i < 4; i++)
#pragma unroll
        for (int j = 0; j < 8; j++)
#pragma unroll
            for (int k = 0; k < 4; k++) acc[i][j][k] = 0.0f;

    // staging: A 512 + B 512 chunks of 16B over 128 threads -> 4+4 each
    auto issue_tile = [&](int kt) {
        if (kt < NKT) {
            uint32_t soff = sbase + (uint32_t)(kt % STAGES) * STAGE_BYTES;
            int kb = kt * BK;
#pragma unroll
            for (int i = 0; i < 4; i++) {
                int id = tid + 128 * i;
                int r = id >> 2, cc = id & 3;
                cp_async16(soff + (uint32_t)((r * PITCH + cc * 8) * 2),
                           Ab + (size_t)r * HDIM + kb + cc * 8);
            }
#pragma unroll
            for (int i = 0; i < 4; i++) {
                int id = tid + 128 * i;
                int r = id >> 2, cc = id & 3;
                cp_async16(soff + A_BYTES + (uint32_t)((r * PITCH + cc * 8) * 2),
                           Bb + (size_t)r * HDIM + kb + cc * 8);
            }
        }
        cp_commit();
    };

    issue_tile(0);
    issue_tile(1);
    issue_tile(2);

    for (int kt = 0; kt < NKT; kt++) {
        cp_wait<STAGES - 2>();
        __syncthreads();
        issue_tile(kt + STAGES - 1);

        const uint32_t buf = sbase + (uint32_t)(kt % STAGES) * STAGE_BYTES;
#pragma unroll
        for (int kk = 0; kk < 2; kk++) {
            uint32_t af[4][4], bf[8][2];
#pragma unroll
            for (int mt = 0; mt < 4; mt++)
                ldsm4(af[mt][0], af[mt][1], af[mt][2], af[mt][3],
                      buf + aoff[mt] + kk * 32);
#pragma unroll
            for (int n2 = 0; n2 < 4; n2++)
                ldsm4(bf[2 * n2][0], bf[2 * n2][1], bf[2 * n2 + 1][0], bf[2 * n2 + 1][1],
                      buf + boff[n2] + kk * 32);
#pragma unroll
            for (int mt = 0; mt < 4; mt++)
#pragma unroll
                for (int nt = 0; nt < 8; nt++)
                    mma_f16(acc[mt][nt][0], acc[mt][nt][1],
                            acc[mt][nt][2], acc[mt][nt][3],
                            af[mt][0], af[mt][1], af[mt][2], af[mt][3],
                            bf[nt][0], bf[nt][1]);
        }
    }

    if (MODE == 0) {
#pragma unroll
        for (int mt = 0; mt < 4; mt++) {
            int r0 = m0 + warpM * 64 + mt * 16 + grp;
#pragma unroll
            for (int nt = 0; nt < 8; nt++) {
                int c0 = n0 + warpN * 64 + nt * 8 + qid * 2;
                *(float2*)&g_wc[(size_t)r0 * HDIM + c0] =
                    make_float2(acc[mt][nt][0], acc[mt][nt][1]);
                *(float2*)&g_wc[(size_t)(r0 + 8) * HDIM + c0] =
                    make_float2(acc[mt][nt][2], acc[mt][nt][3]);
            }
        }
    } else {
        float part[8];
#pragma unroll
        for (int i = 0; i < 8; i++) part[i] = 0.0f;

        const float* biasrow = bias + (size_t)blockIdx.y * HDIM;
        const int bbase = blockIdx.z * BM;

#pragma unroll
        for (int nt = 0; nt < 8; nt++) {
            int c0 = n0 + warpN * 64 + nt * 8 + qid * 2;
            float2 wt2 = *(const float2*)&Wt[c0];
            float2 bi2 = *(const float2*)&biasrow[c0];
#pragma unroll
            for (int mt = 0; mt < 4; mt++) {
                int b0 = bbase + warpM * 64 + mt * 16 + grp;
                float2 w0 = *(const float2*)&g_wc[(size_t)b0 * HDIM + c0];
                float2 w1 = *(const float2*)&g_wc[(size_t)(b0 + 8) * HDIM + c0];
                part[mt * 2]     += fast_tanh(acc[mt][nt][0] + w0.x + bi2.x) * wt2.x
                                  + fast_tanh(acc[mt][nt][1] + w0.y + bi2.y) * wt2.y;
                part[mt * 2 + 1] += fast_tanh(acc[mt][nt][2] + w1.x + bi2.x) * wt2.x
                                  + fast_tanh(acc[mt][nt][3] + w1.y + bi2.y) * wt2.y;
            }
        }
#pragma unroll
        for (int i = 0; i < 8; i++) {
            part[i] += __shfl_xor_sync(0xffffffffu, part[i], 1);
            part[i] += __shfl_xor_sync(0xffffffffu, part[i], 2);
        }
        if (qid == 0) {
#pragma unroll
            for (int mt = 0; mt < 4; mt++) {
                int r0 = m0 + warpM * 64 + mt * 16 + grp;
                atomicAdd(&g_scores[r0],     part[mt * 2]);
                atomicAdd(&g_scores[r0 + 8], part[mt * 2 + 1]);
            }
        }
    }
}

// ---------------------------------------------------------------------------
// Per-b softmax over SEQ scores + weighted sum of fp16 allh rows -> out[b, :]
// ---------------------------------------------------------------------------
__global__ __launch_bounds__(256)
void softmax_combine_kernel(float* __restrict__ out)
{
    int b = blockIdx.x;
    __shared__ float s_alpha[32];

    if (threadIdx.x < 32) {
        int lane = threadIdx.x;
        float v = (lane < SEQ) ? g_scores[lane * BDIM + b] : -1e30f;
        float m = v;
#pragma unroll
        for (int o = 16; o > 0; o >>= 1)
            m = fmaxf(m, __shfl_xor_sync(0xffffffffu, m, o));
        float e = (lane < SEQ) ? __expf(v - m) : 0.0f;
        float sum = e;
#pragma unroll
        for (int o = 16; o > 0; o >>= 1)
            sum += __shfl_xor_sync(0xffffffffu, sum, o);
        s_alpha[lane] = e / sum;
    }
    __syncthreads();

    const uint2* hb = (const uint2*)(g_allh_h + (size_t)b * HDIM) + threadIdx.x;
    float4 accv = make_float4(0.f, 0.f, 0.f, 0.f);
#pragma unroll
    for (int s = 0; s < SEQ; s++) {
        float a = s_alpha[s];
        uint2 v = hb[(size_t)s * (BDIM * HDIM / 4)];
        float2 f0 = __half22float2(*(__half2*)&v.x);
        float2 f1 = __half22float2(*(__half2*)&v.y);
        accv.x += a * f0.x; accv.y += a * f0.y;
        accv.z += a * f1.x; accv.w += a * f1.y;
    }
    ((float4*)(out + (size_t)b * HDIM))[threadIdx.x] = accv;
}

// ------------------------- launch -------------------------
extern "C" void kernel_launch(void* const* d_in, const int* in_sizes, int n_in,
                              void* d_out, int out_size)
{
    const float* c    = (const float*)d_in[0];  // [1, B, H]
    const float* allh = (const float*)d_in[1];  // [S, B, H]
    const float* W    = (const float*)d_in[2];  // [H, H]
    const float* V    = (const float*)d_in[3];  // [H, H]
    const float* bias = (const float*)d_in[4];  // [S, H]
    const float* Wt   = (const float*)d_in[5];  // [H, 1]
    float* out = (float*)d_out;                 // [1, B, H]
    (void)in_sizes; (void)n_in; (void)out_size;

    static bool attr_set = false;
    if (!attr_set) {
        cudaFuncSetAttribute(gemm_f16_kernel<0>,
                             cudaFuncAttributeMaxDynamicSharedMemorySize, SMEM_SIZE);
        cudaFuncSetAttribute(gemm_f16_kernel<1>,
                             cudaFuncAttributeMaxDynamicSharedMemorySize, SMEM_SIZE);
        attr_set = true;
    }

    __half* c_h;    cudaGetSymbolAddress((void**)&c_h,    g_c_h);
    __half* allh_h; cudaGetSymbolAddress((void**)&allh_h, g_allh_h);
    __half* wt_h;   cudaGetSymbolAddress((void**)&wt_h,   g_wt_h);
    __half* vt_h;   cudaGetSymbolAddress((void**)&vt_h,   g_vt_h);

    // 1) housekeeping + fp16 conversions
    zero_scores_kernel<<<MTOT / 256, 256>>>();
    transpose_f16_kernel<<<dim3(32, 32), dim3(32, 8)>>>(W, wt_h);
    transpose_f16_kernel<<<dim3(32, 32), dim3(32, 8)>>>(V, vt_h);
    f32_to_f16_kernel<<<2048, 256>>>(c, c_h, (long long)BDIM * HDIM / 4);
    f32_to_f16_kernel<<<8192, 256>>>(allh, allh_h, (long long)MTOT * HDIM / 4);

    // 2) wc = c @ W   (grid: n-tiles x 1 x b-tiles)
    gemm_f16_kernel<0><<<dim3(HDIM / BN, 1, BDIM / BM), 128, SMEM_SIZE>>>(
        c_h, wt_h, nullptr, nullptr);

    // 3) fused vh GEMM + tanh + score reduction (grid: n-tiles x s x b-tiles)
    gemm_f16_kernel<1><<<dim3(HDIM / BN, SEQ, BDIM / BM), 128, SMEM_SIZE>>>(
        allh_h, vt_h, bias, Wt);

    // 4) softmax over S and weighted combine
    softmax_combine_kernel<<<BDIM, 256>>>(out);
}